// round 4
// baseline (speedup 1.0000x reference)
#include <cuda_runtime.h>

// Problem constants (fixed by reference setup_inputs)
#define NB  8      // batch
#define CCH 512    // channels
#define NH  8      // heads
#define DD  64     // head dim
#define LL  64     // token length
#define CTK 256    // token channels
#define HW  16384  // 128*128 pixels

// Scratch (device globals — no allocations allowed)
__device__ __align__(16) float g_k [NB * CCH * LL];  // [nh][d][l], pre-scaled by 1/8
__device__ __align__(16) float g_vt[NB * CCH * LL];  // [nh][l][d] (transposed V)

// ---- packed f32x2 helpers (FFMA2 is PTX-only; ptxas never auto-fuses) ----
__device__ __forceinline__ unsigned long long pack2(float a, float b) {
    unsigned long long r;
    asm("mov.b64 %0, {%1, %2};" : "=l"(r) : "f"(a), "f"(b));
    return r;
}
__device__ __forceinline__ void unpack2(unsigned long long v, float& a, float& b) {
    asm("mov.b64 {%0, %1}, %2;" : "=f"(a), "=f"(b) : "l"(v));
}
__device__ __forceinline__ void ffma2(unsigned long long& d,
                                      unsigned long long a, unsigned long long b) {
    asm("fma.rn.f32x2 %0, %1, %2, %0;" : "+l"(d) : "l"(a), "l"(b));
}

// ============================================================================
// Kernel 1: fused V/K projections (1x1 conv == pointwise GEMM, K=256)
// K stored d-major (pre-scaled by 1/8), V stored l-major (transposed).
// ============================================================================
__global__ void vk_kernel(const float* __restrict__ token,
                          const float* __restrict__ Wv, const float* __restrict__ bv,
                          const float* __restrict__ Wk, const float* __restrict__ bk) {
    __shared__ float wv_s[CTK];
    __shared__ float wk_s[CTK];
    const int o = blockIdx.x & (CCH - 1);
    const int n = blockIdx.x >> 9;
    const int l = threadIdx.x;

#pragma unroll
    for (int i = 0; i < 4; i++) {
        wv_s[l + 64 * i] = Wv[o * CTK + l + 64 * i];
        wk_s[l + 64 * i] = Wk[o * CTK + l + 64 * i];
    }
    __syncthreads();

    const float* tok = token + n * (CTK * LL) + l;
    float av0 = 0.f, av1 = 0.f, ak0 = 0.f, ak1 = 0.f;
#pragma unroll 8
    for (int ct = 0; ct < CTK; ct += 2) {
        float t0 = tok[ct * LL];
        float t1 = tok[(ct + 1) * LL];
        av0 = fmaf(wv_s[ct],     t0, av0);
        ak0 = fmaf(wk_s[ct],     t0, ak0);
        av1 = fmaf(wv_s[ct + 1], t1, av1);
        ak1 = fmaf(wk_s[ct + 1], t1, ak1);
    }
    float av = av0 + av1 + bv[o];
    float ak = (ak0 + ak1 + bk[o]) * 0.125f;  // 1/sqrt(C/h) = 1/8

    const int h = o >> 6, d = o & 63;
    const int slice = (n * NH + h) * (DD * LL);
    g_k [slice + d * LL + l] = ak;
    g_vt[slice + l * DD + d] = av;
}

// ============================================================================
// Kernel 2: register-blocked attention GEMMs.
// Block = 256 threads (8 warps) = 256 pixels of one (n,h).
// Warp GEMM 32x64x64: thread tile = 8 pixels x 8 outputs (lane = pi*8 + li).
// K/V rows chunk-swizzled for conflict-free stride-32B fragment reads.
// Smem (dynamic 96KB): k_s 16K | v_s 16K | ws 8x8K (per-warp Q then Coef^T).
// ============================================================================
__global__ __launch_bounds__(256, 2)
void attn_kernel(const float* __restrict__ feature, float* __restrict__ out) {
    extern __shared__ __align__(16) float smem[];
    float* k_s = smem;              // [64 d][64 l] swizzled, 4096 floats
    float* v_s = smem + 4096;       // [64 l][64 d] swizzled, 4096 floats
    float* ws  = smem + 8192;       // 8 warps x 2048 floats (Q then Coef^T)

    const int tid  = threadIdx.x;
    const int warp = tid >> 5;
    const int lane = tid & 31;
    const int pi   = lane >> 3;     // pixel group 0..3
    const int li   = lane & 7;      // output group 0..7
    const int tile = blockIdx.x & 63;
    const int nh   = blockIdx.x >> 6;

    // ---- stage K and V tiles with 16B-chunk swizzle c' = (c>>1)|((c&1)<<3) ----
    {
        const float4* gk4 = reinterpret_cast<const float4*>(g_k)  + nh * 1024;
        const float4* gv4 = reinterpret_cast<const float4*>(g_vt) + nh * 1024;
        float4* ks4 = reinterpret_cast<float4*>(k_s);
        float4* vs4 = reinterpret_cast<float4*>(v_s);
#pragma unroll
        for (int i = 0; i < 4; i++) {
            int idx = tid + 256 * i;                 // float4 index, 0..1023
            int row = idx >> 4, c = idx & 15;
            int cs  = (c >> 1) | ((c & 1) << 3);
            ks4[row * 16 + cs] = gk4[idx];
            vs4[row * 16 + cs] = gv4[idx];
        }
    }

    const int pixbase = tile * 256 + warp * 32;
    const float* f = feature + nh * (DD * HW) + pixbase;
    float* wsw = ws + warp * 2048;

    // ---- stage Q tile: [64 d][32 p] per warp, coalesced ----
    {
        const int dq = lane >> 3;           // 0..3
        const int xq = (lane & 7) * 4;      // 0,4,...,28
#pragma unroll
        for (int s = 0; s < 16; s++) {
            int d = s * 4 + dq;
            *reinterpret_cast<float4*>(wsw + d * 32 + xq) =
                *reinterpret_cast<const float4*>(f + d * HW + xq);
        }
    }
    __syncthreads();

    // ---- GEMM1: logits[32p][64l] = Q[32p][64d] * K[64d][64l] ----
    unsigned long long acc[8][4];
#pragma unroll
    for (int j = 0; j < 8; j++)
#pragma unroll
        for (int ii = 0; ii < 4; ii++) acc[j][ii] = 0ull;

#pragma unroll 4
    for (int d = 0; d < DD; d++) {
        float4 qf0 = *reinterpret_cast<const float4*>(wsw + d * 32 + pi * 8);
        float4 qf1 = *reinterpret_cast<const float4*>(wsw + d * 32 + pi * 8 + 4);
        ulonglong2 ka = *reinterpret_cast<const ulonglong2*>(k_s + d * 64 + li * 4);
        ulonglong2 kb = *reinterpret_cast<const ulonglong2*>(k_s + d * 64 + 32 + li * 4);
        unsigned long long qq[8];
        qq[0] = pack2(qf0.x, qf0.x); qq[1] = pack2(qf0.y, qf0.y);
        qq[2] = pack2(qf0.z, qf0.z); qq[3] = pack2(qf0.w, qf0.w);
        qq[4] = pack2(qf1.x, qf1.x); qq[5] = pack2(qf1.y, qf1.y);
        qq[6] = pack2(qf1.z, qf1.z); qq[7] = pack2(qf1.w, qf1.w);
#pragma unroll
        for (int j = 0; j < 8; j++) {
            ffma2(acc[j][0], qq[j], ka.x);
            ffma2(acc[j][1], qq[j], ka.y);
            ffma2(acc[j][2], qq[j], kb.x);
            ffma2(acc[j][3], qq[j], kb.y);
        }
    }

    // ---- softmax per pixel row (8 rows x 8 local l; reduce over 8 li-lanes) ----
    float lg[8][8];
#pragma unroll
    for (int j = 0; j < 8; j++)
#pragma unroll
        for (int ii = 0; ii < 4; ii++) unpack2(acc[j][ii], lg[j][2 * ii], lg[j][2 * ii + 1]);

    float inv[8];
#pragma unroll
    for (int j = 0; j < 8; j++) {
        float m = lg[j][0];
#pragma unroll
        for (int i = 1; i < 8; i++) m = fmaxf(m, lg[j][i]);
        m = fmaxf(m, __shfl_xor_sync(0xffffffffu, m, 1));
        m = fmaxf(m, __shfl_xor_sync(0xffffffffu, m, 2));
        m = fmaxf(m, __shfl_xor_sync(0xffffffffu, m, 4));
        float s = 0.f;
#pragma unroll
        for (int i = 0; i < 8; i++) { lg[j][i] = __expf(lg[j][i] - m); s += lg[j][i]; }
        s += __shfl_xor_sync(0xffffffffu, s, 1);
        s += __shfl_xor_sync(0xffffffffu, s, 2);
        s += __shfl_xor_sync(0xffffffffu, s, 4);
        inv[j] = __frcp_rn(s);
    }

    // ---- write Coef^T [64 l][32 p] into ws (overwrites Q) ----
    __syncwarp();
#pragma unroll
    for (int i = 0; i < 8; i++) {
        float4 a, b;
        a.x = lg[0][i] * inv[0]; a.y = lg[1][i] * inv[1];
        a.z = lg[2][i] * inv[2]; a.w = lg[3][i] * inv[3];
        b.x = lg[4][i] * inv[4]; b.y = lg[5][i] * inv[5];
        b.z = lg[6][i] * inv[6]; b.w = lg[7][i] * inv[7];
        *reinterpret_cast<float4*>(wsw + (li * 8 + i) * 32 + pi * 8)     = a;
        *reinterpret_cast<float4*>(wsw + (li * 8 + i) * 32 + pi * 8 + 4) = b;
    }
    __syncwarp();

    // ---- GEMM2: out[32p][64d] = Coef[32p][64l] * V[64l][64d] ----
    unsigned long long pr[8][4];
#pragma unroll
    for (int j = 0; j < 8; j++)
#pragma unroll
        for (int ii = 0; ii < 4; ii++) pr[j][ii] = 0ull;

#pragma unroll 4
    for (int l = 0; l < LL; l++) {
        float4 cf0 = *reinterpret_cast<const float4*>(wsw + l * 32 + pi * 8);
        float4 cf1 = *reinterpret_cast<const float4*>(wsw + l * 32 + pi * 8 + 4);
        ulonglong2 va = *reinterpret_cast<const ulonglong2*>(v_s + l * 64 + li * 4);
        ulonglong2 vb = *reinterpret_cast<const ulonglong2*>(v_s + l * 64 + 32 + li * 4);
        unsigned long long cc[8];
        cc[0] = pack2(cf0.x, cf0.x); cc[1] = pack2(cf0.y, cf0.y);
        cc[2] = pack2(cf0.z, cf0.z); cc[3] = pack2(cf0.w, cf0.w);
        cc[4] = pack2(cf1.x, cf1.x); cc[5] = pack2(cf1.y, cf1.y);
        cc[6] = pack2(cf1.z, cf1.z); cc[7] = pack2(cf1.w, cf1.w);
#pragma unroll
        for (int j = 0; j < 8; j++) {
            ffma2(pr[j][0], cc[j], va.x);
            ffma2(pr[j][1], cc[j], va.y);
            ffma2(pr[j][2], cc[j], vb.x);
            ffma2(pr[j][3], cc[j], vb.y);
        }
    }

    // ---- epilogue: residual add (feature re-read, L2-hot) + store ----
    float* o = out + nh * (DD * HW) + pixbase;
#pragma unroll
    for (int ii = 0; ii < 4; ii++) {
        int d0 = li * 8 + 2 * ii;
        float p0[8], p1[8];
#pragma unroll
        for (int j = 0; j < 8; j++) unpack2(pr[j][ii], p0[j], p1[j]);

        float4 fa0 = *reinterpret_cast<const float4*>(f + d0 * HW + pi * 8);
        float4 fa1 = *reinterpret_cast<const float4*>(f + d0 * HW + pi * 8 + 4);
        float4 fb0 = *reinterpret_cast<const float4*>(f + (d0 + 1) * HW + pi * 8);
        float4 fb1 = *reinterpret_cast<const float4*>(f + (d0 + 1) * HW + pi * 8 + 4);

        float4 oa0, oa1, ob0, ob1;
        oa0.x = fa0.x + p0[0]; oa0.y = fa0.y + p0[1]; oa0.z = fa0.z + p0[2]; oa0.w = fa0.w + p0[3];
        oa1.x = fa1.x + p0[4]; oa1.y = fa1.y + p0[5]; oa1.z = fa1.z + p0[6]; oa1.w = fa1.w + p0[7];
        ob0.x = fb0.x + p1[0]; ob0.y = fb0.y + p1[1]; ob0.z = fb0.z + p1[2]; ob0.w = fb0.w + p1[3];
        ob1.x = fb1.x + p1[4]; ob1.y = fb1.y + p1[5]; ob1.z = fb1.z + p1[6]; ob1.w = fb1.w + p1[7];

        *reinterpret_cast<float4*>(o + d0 * HW + pi * 8)           = oa0;
        *reinterpret_cast<float4*>(o + d0 * HW + pi * 8 + 4)       = oa1;
        *reinterpret_cast<float4*>(o + (d0 + 1) * HW + pi * 8)     = ob0;
        *reinterpret_cast<float4*>(o + (d0 + 1) * HW + pi * 8 + 4) = ob1;
    }
}

// ============================================================================
extern "C" void kernel_launch(void* const* d_in, const int* in_sizes, int n_in,
                              void* d_out, int out_size) {
    const float* feature = (const float*)d_in[0];
    const float* token   = (const float*)d_in[1];
    const float* Wv      = (const float*)d_in[2];
    const float* bv      = (const float*)d_in[3];
    const float* Wk      = (const float*)d_in[4];
    const float* bk      = (const float*)d_in[5];
    float* out = (float*)d_out;

    const int smem_bytes = 96 * 1024;
    cudaFuncSetAttribute(attn_kernel, cudaFuncAttributeMaxDynamicSharedMemorySize, smem_bytes);

    vk_kernel<<<NB * CCH, 64>>>(token, Wv, bv, Wk, bk);
    attn_kernel<<<NB * NH * 64, 256, smem_bytes>>>(feature, out);
}

// round 6
// speedup vs baseline: 1.4197x; 1.4197x over previous
#include <cuda_runtime.h>
#include <cstdint>

// Problem constants (fixed by reference setup_inputs)
#define NB  8      // batch
#define CCH 512    // channels
#define NH  8      // heads
#define DD  64     // head dim
#define LL  64     // token length
#define CTK 256    // token channels
#define HW  16384  // 128*128 pixels

// Scratch (device globals — no allocations allowed)
__device__ __align__(16) float g_k[NB * CCH * LL];  // [nh][l][d] tf32-rounded, pre-scaled 1/8
__device__ __align__(16) float g_v[NB * CCH * LL];  // [nh][d][l] tf32-rounded

__device__ __forceinline__ uint32_t f2tf32(float x) {
    uint32_t r;
    asm("cvt.rn.tf32.f32 %0, %1;" : "=r"(r) : "f"(x));
    return r;
}

// m16n8k8 tf32 HMMA (base-target instruction, works at compute_103)
__device__ __forceinline__ void mma_tf32(float c[4],
                                         uint32_t a0, uint32_t a1, uint32_t a2, uint32_t a3,
                                         uint32_t b0, uint32_t b1) {
    asm volatile(
        "mma.sync.aligned.m16n8k8.row.col.f32.tf32.tf32.f32 "
        "{%0,%1,%2,%3}, {%4,%5,%6,%7}, {%8,%9}, {%0,%1,%2,%3};"
        : "+f"(c[0]), "+f"(c[1]), "+f"(c[2]), "+f"(c[3])
        : "r"(a0), "r"(a1), "r"(a2), "r"(a3), "r"(b0), "r"(b1));
}

// ============================================================================
// Kernel 1: fused V/K projections (1x1 conv, K=256).
//   g_k[nh][l][d] = K/8 (tf32-rounded)  — GEMM1 B operand (k-dim = d)
//   g_v[nh][d][l] = V   (tf32-rounded)  — GEMM2 B operand (k-dim = l)
// ============================================================================
__global__ void vk_kernel(const float* __restrict__ token,
                          const float* __restrict__ Wv, const float* __restrict__ bv,
                          const float* __restrict__ Wk, const float* __restrict__ bk) {
    __shared__ float wv_s[CTK];
    __shared__ float wk_s[CTK];
    const int o = blockIdx.x & (CCH - 1);
    const int n = blockIdx.x >> 9;
    const int l = threadIdx.x;

#pragma unroll
    for (int i = 0; i < 4; i++) {
        wv_s[l + 64 * i] = Wv[o * CTK + l + 64 * i];
        wk_s[l + 64 * i] = Wk[o * CTK + l + 64 * i];
    }
    __syncthreads();

    const float* tok = token + n * (CTK * LL) + l;
    float av0 = 0.f, av1 = 0.f, ak0 = 0.f, ak1 = 0.f;
#pragma unroll 8
    for (int ct = 0; ct < CTK; ct += 2) {
        float t0 = tok[ct * LL];
        float t1 = tok[(ct + 1) * LL];
        av0 = fmaf(wv_s[ct],     t0, av0);
        ak0 = fmaf(wk_s[ct],     t0, ak0);
        av1 = fmaf(wv_s[ct + 1], t1, av1);
        ak1 = fmaf(wk_s[ct + 1], t1, ak1);
    }
    float av = av0 + av1 + bv[o];
    float ak = (ak0 + ak1 + bk[o]) * 0.125f;  // 1/sqrt(C/h) = 1/8

    const int h = o >> 6, d = o & 63;
    const int slice = (n * NH + h) * (DD * LL);
    g_k[slice + l * DD + d] = __uint_as_float(f2tf32(ak));  // [l][d]
    g_v[slice + d * LL + l] = __uint_as_float(f2tf32(av));  // [d][l]
}

// ============================================================================
// Kernel 2: mma.sync tf32 attention.
// CTA = 128 threads = 64 pixels; warp = 16 pixels (one m16 row tile).
//   GEMM1: logits[16p][64l] = Q[16p][64d] * K[64l][64d]^T   (8 n-tiles x 8 k-steps)
//   softmax in fragments (quad shfl reductions)
//   coef D-frag -> A-frag via shfl.idx remap (register-only)
//   GEMM2: proj[16p][64d] = coef[16p][64l] * V[64d][64l]^T
//   residual reconstructed from kept Q registers via shfl.idx (no feature re-read)
// K/V smem: packed (b0,b1) float2 pairs + rotation swizzle -> 1 conflict-free
// LDS.64 per B-fragment.
// ============================================================================
__global__ __launch_bounds__(128, 3)
void attn_kernel(const float* __restrict__ feature, float* __restrict__ out) {
    __shared__ __align__(16) float ks[DD * LL];
    __shared__ __align__(16) float vs[DD * LL];

    const int tid  = threadIdx.x;
    const int lane = tid & 31;
    const int warp = tid >> 5;
    const int gid  = lane >> 2;   // groupID (fragment row)
    const int qid  = lane & 3;    // threadID-in-group (fragment col)
    const int nh   = blockIdx.x >> 8;
    const int tile = blockIdx.x & 255;
    const int pixbase = tile * 64 + warp * 16;

    // ---- stage K/V: element (row, col) -> word row*64 + 2*((4*(col/8)+(col&3)+4*row)&31) + ((col>>2)&1)
    // so fragment (b0=col, b1=col+4) is one aligned float2, bank = lane-unique.
    {
        const float* gk = g_k + nh * 4096;
        const float* gv = g_v + nh * 4096;
#pragma unroll
        for (int i = 0; i < 32; i++) {
            int idx = tid + 128 * i;
            int row = idx >> 6, col = idx & 63;
            int kt = col >> 3, q = col & 3, w = (col >> 2) & 1;
            int addr = row * 64 + 2 * ((4 * kt + q + 4 * row) & 31) + w;
            ks[addr] = gk[idx];
            vs[addr] = gv[idx];
        }
    }

    // ---- load Q A-fragments straight from gmem; keep originals for residual ----
    const float* f = feature + nh * (DD * HW) + pixbase;
    float qf[32];  // [kt][4]: a0=(gid, 8kt+qid) a1=(gid+8, ..) a2=(gid, 8kt+qid+4) a3=(gid+8, ..)
#pragma unroll
    for (int kt = 0; kt < 8; kt++) {
        qf[4 * kt + 0] = f[(8 * kt + qid) * HW + gid];
        qf[4 * kt + 1] = f[(8 * kt + qid) * HW + gid + 8];
        qf[4 * kt + 2] = f[(8 * kt + qid + 4) * HW + gid];
        qf[4 * kt + 3] = f[(8 * kt + qid + 4) * HW + gid + 8];
    }
    __syncthreads();

    const int rot = (qid + 4 * gid) & 31;  // per-lane rotation base

    // ---- GEMM1: acc[8 n-tiles][4] ----
    float acc[32];
#pragma unroll
    for (int i = 0; i < 32; i++) acc[i] = 0.f;
#pragma unroll
    for (int kt = 0; kt < 8; kt++) {
        uint32_t a0 = f2tf32(qf[4 * kt + 0]);
        uint32_t a1 = f2tf32(qf[4 * kt + 1]);
        uint32_t a2 = f2tf32(qf[4 * kt + 2]);
        uint32_t a3 = f2tf32(qf[4 * kt + 3]);
        const int c2 = (4 * kt + rot) & 31;
#pragma unroll
        for (int j = 0; j < 8; j++) {
            float2 b = *reinterpret_cast<const float2*>(&ks[(8 * j + gid) * 64 + 2 * c2]);
            mma_tf32(&acc[4 * j], a0, a1, a2, a3,
                     __float_as_uint(b.x), __float_as_uint(b.y));
        }
    }

    // ---- softmax in fragments: rows gid (c0,c1) and gid+8 (c2,c3) ----
    {
        float m0 = -1e30f, m1 = -1e30f;
#pragma unroll
        for (int j = 0; j < 8; j++) {
            m0 = fmaxf(m0, fmaxf(acc[4 * j + 0], acc[4 * j + 1]));
            m1 = fmaxf(m1, fmaxf(acc[4 * j + 2], acc[4 * j + 3]));
        }
        m0 = fmaxf(m0, __shfl_xor_sync(0xffffffffu, m0, 1));
        m0 = fmaxf(m0, __shfl_xor_sync(0xffffffffu, m0, 2));
        m1 = fmaxf(m1, __shfl_xor_sync(0xffffffffu, m1, 1));
        m1 = fmaxf(m1, __shfl_xor_sync(0xffffffffu, m1, 2));
        float s0 = 0.f, s1 = 0.f;
#pragma unroll
        for (int j = 0; j < 8; j++) {
            acc[4 * j + 0] = __expf(acc[4 * j + 0] - m0); s0 += acc[4 * j + 0];
            acc[4 * j + 1] = __expf(acc[4 * j + 1] - m0); s0 += acc[4 * j + 1];
            acc[4 * j + 2] = __expf(acc[4 * j + 2] - m1); s1 += acc[4 * j + 2];
            acc[4 * j + 3] = __expf(acc[4 * j + 3] - m1); s1 += acc[4 * j + 3];
        }
        s0 += __shfl_xor_sync(0xffffffffu, s0, 1);
        s0 += __shfl_xor_sync(0xffffffffu, s0, 2);
        s1 += __shfl_xor_sync(0xffffffffu, s1, 1);
        s1 += __shfl_xor_sync(0xffffffffu, s1, 2);
        const float inv0 = __frcp_rn(s0);
        const float inv1 = __frcp_rn(s1);
#pragma unroll
        for (int j = 0; j < 8; j++) {
            acc[4 * j + 0] = __uint_as_float(f2tf32(acc[4 * j + 0] * inv0));
            acc[4 * j + 1] = __uint_as_float(f2tf32(acc[4 * j + 1] * inv0));
            acc[4 * j + 2] = __uint_as_float(f2tf32(acc[4 * j + 2] * inv1));
            acc[4 * j + 3] = __uint_as_float(f2tf32(acc[4 * j + 3] * inv1));
        }
    }

    // ---- remap coef D-fragments -> A-fragments (k-dim = l) via shfl.idx ----
    // A target (row p, col c): source lane 4*(p%8) + (c>>1), reg (c&1) + 2*(p>=8)
    uint32_t ca[32];  // [l-ktile][4]
    {
        const int s0 = 4 * gid + (qid >> 1);
        const int s1 = s0 + 2;
        const bool odd = qid & 1;
#pragma unroll
        for (int j = 0; j < 8; j++) {
            float v00 = __shfl_sync(0xffffffffu, acc[4 * j + 0], s0);
            float v01 = __shfl_sync(0xffffffffu, acc[4 * j + 1], s0);
            float v10 = __shfl_sync(0xffffffffu, acc[4 * j + 2], s0);
            float v11 = __shfl_sync(0xffffffffu, acc[4 * j + 3], s0);
            float w00 = __shfl_sync(0xffffffffu, acc[4 * j + 0], s1);
            float w01 = __shfl_sync(0xffffffffu, acc[4 * j + 1], s1);
            float w10 = __shfl_sync(0xffffffffu, acc[4 * j + 2], s1);
            float w11 = __shfl_sync(0xffffffffu, acc[4 * j + 3], s1);
            ca[4 * j + 0] = __float_as_uint(odd ? v01 : v00);
            ca[4 * j + 1] = __float_as_uint(odd ? v11 : v10);
            ca[4 * j + 2] = __float_as_uint(odd ? w01 : w00);
            ca[4 * j + 3] = __float_as_uint(odd ? w11 : w10);
        }
    }

    // ---- GEMM2: pr[8 d-tiles][4] = coef * V^T ----
    float pr[32];
#pragma unroll
    for (int i = 0; i < 32; i++) pr[i] = 0.f;
#pragma unroll
    for (int t = 0; t < 8; t++) {
        const int c2 = (4 * t + rot) & 31;
#pragma unroll
        for (int j = 0; j < 8; j++) {
            float2 b = *reinterpret_cast<const float2*>(&vs[(8 * j + gid) * 64 + 2 * c2]);
            mma_tf32(&pr[4 * j], ca[4 * t + 0], ca[4 * t + 1], ca[4 * t + 2], ca[4 * t + 3],
                     __float_as_uint(b.x), __float_as_uint(b.y));
        }
    }

    // ---- epilogue: residual from kept Q regs (shfl remap), coalesced stores ----
    {
        float* o = out + nh * (DD * HW) + pixbase;
        const int sl0 = 4 * gid + ((2 * qid) & 3);
        const int sl1 = 4 * gid + ((2 * qid + 1) & 3);
        const bool w = qid >> 1;
#pragma unroll
        for (int j = 0; j < 8; j++) {
            float f00 = __shfl_sync(0xffffffffu, qf[4 * j + 0], sl0);
            float f02 = __shfl_sync(0xffffffffu, qf[4 * j + 2], sl0);
            float f01 = __shfl_sync(0xffffffffu, qf[4 * j + 1], sl0);
            float f03 = __shfl_sync(0xffffffffu, qf[4 * j + 3], sl0);
            float g00 = __shfl_sync(0xffffffffu, qf[4 * j + 0], sl1);
            float g02 = __shfl_sync(0xffffffffu, qf[4 * j + 2], sl1);
            float g01 = __shfl_sync(0xffffffffu, qf[4 * j + 1], sl1);
            float g03 = __shfl_sync(0xffffffffu, qf[4 * j + 3], sl1);
            float r_c0 = w ? f02 : f00;   // (row gid,   col d0)
            float r_c2 = w ? f03 : f01;   // (row gid+8, col d0)
            float r_c1 = w ? g02 : g00;   // (row gid,   col d0+1)
            float r_c3 = w ? g03 : g01;   // (row gid+8, col d0+1)
            const int d0 = 8 * j + 2 * qid;
            o[d0 * HW + gid]           = pr[4 * j + 0] + r_c0;
            o[(d0 + 1) * HW + gid]     = pr[4 * j + 1] + r_c1;
            o[d0 * HW + gid + 8]       = pr[4 * j + 2] + r_c2;
            o[(d0 + 1) * HW + gid + 8] = pr[4 * j + 3] + r_c3;
        }
    }
}

// ============================================================================
extern "C" void kernel_launch(void* const* d_in, const int* in_sizes, int n_in,
                              void* d_out, int out_size) {
    const float* feature = (const float*)d_in[0];
    const float* token   = (const float*)d_in[1];
    const float* Wv      = (const float*)d_in[2];
    const float* bv      = (const float*)d_in[3];
    const float* Wk      = (const float*)d_in[4];
    const float* bk      = (const float*)d_in[5];
    float* out = (float*)d_out;

    vk_kernel<<<NB * CCH, 64>>>(token, Wv, bv, Wk, bk);
    attn_kernel<<<NB * NH * 256, 128>>>(feature, out);
}

// round 7
// speedup vs baseline: 2.4985x; 1.7598x over previous
#include <cuda_runtime.h>
#include <cstdint>

// Problem constants (fixed by reference setup_inputs)
#define NB  8      // batch
#define CCH 512    // channels
#define NH  8      // heads
#define DD  64     // head dim
#define LL  64     // token length
#define CTK 256    // token channels
#define HW  16384  // 128*128 pixels

// Scratch (device globals — no allocations allowed)
__device__ __align__(16) float g_k[NB * CCH * LL];  // [nh][l][d] tf32-rounded, pre-scaled 1/8
__device__ __align__(16) float g_v[NB * CCH * LL];  // [nh][d][l] tf32-rounded

__device__ __forceinline__ uint32_t f2tf32(float x) {
    uint32_t r;
    asm("cvt.rn.tf32.f32 %0, %1;" : "=r"(r) : "f"(x));
    return r;
}

// m16n8k8 tf32 HMMA (base-target instruction, works at compute_103)
__device__ __forceinline__ void mma_tf32(float* c,
                                         uint32_t a0, uint32_t a1, uint32_t a2, uint32_t a3,
                                         uint32_t b0, uint32_t b1) {
    asm volatile(
        "mma.sync.aligned.m16n8k8.row.col.f32.tf32.tf32.f32 "
        "{%0,%1,%2,%3}, {%4,%5,%6,%7}, {%8,%9}, {%0,%1,%2,%3};"
        : "+f"(c[0]), "+f"(c[1]), "+f"(c[2]), "+f"(c[3])
        : "r"(a0), "r"(a1), "r"(a2), "r"(a3), "r"(b0), "r"(b1));
}

// ============================================================================
// Kernel 1: fused V/K projections (1x1 conv, K=256).
//   g_k[nh][l][d] = K/8 (tf32-rounded)  — GEMM1 B operand (k-dim = d)
//   g_v[nh][d][l] = V   (tf32-rounded)  — GEMM2 B operand (k-dim = l)
// ============================================================================
__global__ void vk_kernel(const float* __restrict__ token,
                          const float* __restrict__ Wv, const float* __restrict__ bv,
                          const float* __restrict__ Wk, const float* __restrict__ bk) {
    __shared__ float wv_s[CTK];
    __shared__ float wk_s[CTK];
    const int o = blockIdx.x & (CCH - 1);
    const int n = blockIdx.x >> 9;
    const int l = threadIdx.x;

#pragma unroll
    for (int i = 0; i < 4; i++) {
        wv_s[l + 64 * i] = Wv[o * CTK + l + 64 * i];
        wk_s[l + 64 * i] = Wk[o * CTK + l + 64 * i];
    }
    __syncthreads();

    const float* tok = token + n * (CTK * LL) + l;
    float av0 = 0.f, av1 = 0.f, ak0 = 0.f, ak1 = 0.f;
#pragma unroll 8
    for (int ct = 0; ct < CTK; ct += 2) {
        float t0 = tok[ct * LL];
        float t1 = tok[(ct + 1) * LL];
        av0 = fmaf(wv_s[ct],     t0, av0);
        ak0 = fmaf(wk_s[ct],     t0, ak0);
        av1 = fmaf(wv_s[ct + 1], t1, av1);
        ak1 = fmaf(wk_s[ct + 1], t1, ak1);
    }
    float av = av0 + av1 + bv[o];
    float ak = (ak0 + ak1 + bk[o]) * 0.125f;  // 1/sqrt(C/h) = 1/8

    const int h = o >> 6, d = o & 63;
    const int slice = (n * NH + h) * (DD * LL);
    g_k[slice + l * DD + d] = __uint_as_float(f2tf32(ak));  // [l][d]
    g_v[slice + d * LL + l] = __uint_as_float(f2tf32(av));  // [d][l]
}

// ============================================================================
// Kernel 2: mma.sync tf32 attention, M=32 per warp (two m16 tiles).
// CTA = 128 threads = 128 pixels of one (n,h); grid = 64 * 128 = 8192.
//   GEMM1: logits[32p][64l] = Q * K^T   (8 k-steps x 8 n-tiles x 2 m-tiles,
//          B-fragment shared across both m-tiles)
//   softmax in fragments; coef remapped D->A in place via quad shuffles
//   GEMM2: proj[32p][64d] = coef * V^T
//   epilogue: D-frags -> smem (conflict-free) -> coalesced float4
//             residual-add (feature reload, L1/L2-hot) + store
// ============================================================================
__global__ __launch_bounds__(128, 3)
void attn_kernel(const float* __restrict__ feature, float* __restrict__ out) {
    __shared__ __align__(16) float sm[64 * 132];   // K/V staging, then epilogue buffer
    float* ks = sm;                                 // [64 l][64 d] packed-pair rotated
    float* vs = sm + 4096;                          // [64 d][64 l] packed-pair rotated

    const int tid  = threadIdx.x;
    const int lane = tid & 31;
    const int warp = tid >> 5;
    const int gid  = lane >> 2;   // fragment row group
    const int qid  = lane & 3;    // fragment col group
    const int nh   = blockIdx.x >> 7;
    const int tile = blockIdx.x & 127;

    // ---- stage K/V: (row, col) -> row*64 + 2*((4*(col/8)+(col&3)+4*row)&31) + ((col>>2)&1)
    // (fragment pair (col, col+4) becomes one aligned, bank-unique float2)
    {
        const float4* gk4 = reinterpret_cast<const float4*>(g_k) + nh * 1024;
        const float4* gv4 = reinterpret_cast<const float4*>(g_v) + nh * 1024;
#pragma unroll
        for (int i = 0; i < 8; i++) {
            int idx = tid + 128 * i;             // float4 index 0..1023
            int row = idx >> 4, c = idx & 15;
            int w = c & 1, ktb = 4 * (c >> 1) + 4 * row;
            float4 kv = gk4[idx];
            float4 vv = gv4[idx];
            float* kb = ks + row * 64 + w;
            float* vb = vs + row * 64 + w;
            kb[2 * ((ktb + 0) & 31)] = kv.x;  vb[2 * ((ktb + 0) & 31)] = vv.x;
            kb[2 * ((ktb + 1) & 31)] = kv.y;  vb[2 * ((ktb + 1) & 31)] = vv.y;
            kb[2 * ((ktb + 2) & 31)] = kv.z;  vb[2 * ((ktb + 2) & 31)] = vv.z;
            kb[2 * ((ktb + 3) & 31)] = kv.w;  vb[2 * ((ktb + 3) & 31)] = vv.w;
        }
    }

    const float* f = feature + nh * (DD * HW) + tile * 128 + warp * 32;
    const int rot = (qid + 4 * gid) & 31;

    __syncthreads();

    // ---- GEMM1: acc[2 m-tiles][8 n-tiles][4] ----
    float acc[64];
#pragma unroll
    for (int i = 0; i < 64; i++) acc[i] = 0.f;
#pragma unroll
    for (int kt = 0; kt < 8; kt++) {
        uint32_t a[2][4];
#pragma unroll
        for (int T = 0; T < 2; T++) {
            a[T][0] = f2tf32(f[(8 * kt + qid) * HW + 16 * T + gid]);
            a[T][1] = f2tf32(f[(8 * kt + qid) * HW + 16 * T + gid + 8]);
            a[T][2] = f2tf32(f[(8 * kt + qid + 4) * HW + 16 * T + gid]);
            a[T][3] = f2tf32(f[(8 * kt + qid + 4) * HW + 16 * T + gid + 8]);
        }
        const int c2 = (4 * kt + rot) & 31;
#pragma unroll
        for (int j = 0; j < 8; j++) {
            float2 b = *reinterpret_cast<const float2*>(&ks[(8 * j + gid) * 64 + 2 * c2]);
            uint32_t b0 = __float_as_uint(b.x), b1 = __float_as_uint(b.y);
            mma_tf32(&acc[4 * j],      a[0][0], a[0][1], a[0][2], a[0][3], b0, b1);
            mma_tf32(&acc[32 + 4 * j], a[1][0], a[1][1], a[1][2], a[1][3], b0, b1);
        }
    }

    // ---- softmax per m-tile (rows gid via c0/c1, gid+8 via c2/c3) ----
#pragma unroll
    for (int T = 0; T < 2; T++) {
        float* ac = acc + 32 * T;
        float m0 = -1e30f, m1 = -1e30f;
#pragma unroll
        for (int j = 0; j < 8; j++) {
            m0 = fmaxf(m0, fmaxf(ac[4 * j + 0], ac[4 * j + 1]));
            m1 = fmaxf(m1, fmaxf(ac[4 * j + 2], ac[4 * j + 3]));
        }
        m0 = fmaxf(m0, __shfl_xor_sync(0xffffffffu, m0, 1));
        m0 = fmaxf(m0, __shfl_xor_sync(0xffffffffu, m0, 2));
        m1 = fmaxf(m1, __shfl_xor_sync(0xffffffffu, m1, 1));
        m1 = fmaxf(m1, __shfl_xor_sync(0xffffffffu, m1, 2));
        float s0 = 0.f, s1 = 0.f;
#pragma unroll
        for (int j = 0; j < 8; j++) {
            ac[4 * j + 0] = __expf(ac[4 * j + 0] - m0); s0 += ac[4 * j + 0];
            ac[4 * j + 1] = __expf(ac[4 * j + 1] - m0); s0 += ac[4 * j + 1];
            ac[4 * j + 2] = __expf(ac[4 * j + 2] - m1); s1 += ac[4 * j + 2];
            ac[4 * j + 3] = __expf(ac[4 * j + 3] - m1); s1 += ac[4 * j + 3];
        }
        s0 += __shfl_xor_sync(0xffffffffu, s0, 1);
        s0 += __shfl_xor_sync(0xffffffffu, s0, 2);
        s1 += __shfl_xor_sync(0xffffffffu, s1, 1);
        s1 += __shfl_xor_sync(0xffffffffu, s1, 2);
        const float inv0 = __frcp_rn(s0);
        const float inv1 = __frcp_rn(s1);
#pragma unroll
        for (int j = 0; j < 8; j++) {
            ac[4 * j + 0] = __uint_as_float(f2tf32(ac[4 * j + 0] * inv0));
            ac[4 * j + 1] = __uint_as_float(f2tf32(ac[4 * j + 1] * inv0));
            ac[4 * j + 2] = __uint_as_float(f2tf32(ac[4 * j + 2] * inv1));
            ac[4 * j + 3] = __uint_as_float(f2tf32(ac[4 * j + 3] * inv1));
        }
    }

    // ---- remap coef D-frag -> A-frag in place (within each k/n tile t) ----
    // A(row p, col qid+8t / qid+4+8t) sources D cols {2q,2q+1} of quad lanes.
    {
        const int s0 = 4 * gid + (qid >> 1);
        const int s1 = s0 + 2;
        const bool odd = qid & 1;
#pragma unroll
        for (int T = 0; T < 2; T++) {
            float* ac = acc + 32 * T;
#pragma unroll
            for (int t = 0; t < 8; t++) {
                float v0 = __shfl_sync(0xffffffffu, ac[4 * t + 0], s0);
                float v1 = __shfl_sync(0xffffffffu, ac[4 * t + 1], s0);
                float v2 = __shfl_sync(0xffffffffu, ac[4 * t + 2], s0);
                float v3 = __shfl_sync(0xffffffffu, ac[4 * t + 3], s0);
                float w0 = __shfl_sync(0xffffffffu, ac[4 * t + 0], s1);
                float w1 = __shfl_sync(0xffffffffu, ac[4 * t + 1], s1);
                float w2 = __shfl_sync(0xffffffffu, ac[4 * t + 2], s1);
                float w3 = __shfl_sync(0xffffffffu, ac[4 * t + 3], s1);
                ac[4 * t + 0] = odd ? v1 : v0;
                ac[4 * t + 1] = odd ? v3 : v2;
                ac[4 * t + 2] = odd ? w1 : w0;
                ac[4 * t + 3] = odd ? w3 : w2;
            }
        }
    }

    // ---- GEMM2: pr[2][8 d-tiles][4] = coef * V^T ----
    float pr[64];
#pragma unroll
    for (int i = 0; i < 64; i++) pr[i] = 0.f;
#pragma unroll
    for (int t = 0; t < 8; t++) {
        const int c2 = (4 * t + rot) & 31;
#pragma unroll
        for (int j = 0; j < 8; j++) {
            float2 b = *reinterpret_cast<const float2*>(&vs[(8 * j + gid) * 64 + 2 * c2]);
            uint32_t b0 = __float_as_uint(b.x), b1 = __float_as_uint(b.y);
            mma_tf32(&pr[4 * j],
                     __float_as_uint(acc[4 * t + 0]), __float_as_uint(acc[4 * t + 1]),
                     __float_as_uint(acc[4 * t + 2]), __float_as_uint(acc[4 * t + 3]), b0, b1);
            mma_tf32(&pr[32 + 4 * j],
                     __float_as_uint(acc[32 + 4 * t + 0]), __float_as_uint(acc[32 + 4 * t + 1]),
                     __float_as_uint(acc[32 + 4 * t + 2]), __float_as_uint(acc[32 + 4 * t + 3]), b0, b1);
        }
    }

    // ---- epilogue: frags -> smem [d][132] (conflict-free), then coalesced ----
    __syncthreads();   // K/V tiles dead for all warps
#pragma unroll
    for (int T = 0; T < 2; T++) {
#pragma unroll
        for (int j = 0; j < 8; j++) {
            int px = warp * 32 + 16 * T + gid;
            int d  = 8 * j + 2 * qid;
            sm[d * 132 + px]           = pr[32 * T + 4 * j + 0];
            sm[(d + 1) * 132 + px]     = pr[32 * T + 4 * j + 1];
            sm[d * 132 + px + 8]       = pr[32 * T + 4 * j + 2];
            sm[(d + 1) * 132 + px + 8] = pr[32 * T + 4 * j + 3];
        }
    }
    __syncthreads();

    {
        const float* fb = feature + nh * (DD * HW) + tile * 128;
        float*       ob = out     + nh * (DD * HW) + tile * 128;
        const int px4 = lane * 4;
#pragma unroll
        for (int i = 0; i < 16; i++) {
            int d = warp * 16 + i;
            float4 p  = *reinterpret_cast<const float4*>(&sm[d * 132 + px4]);
            float4 fv = *reinterpret_cast<const float4*>(&fb[d * HW + px4]);
            float4 ov;
            ov.x = fv.x + p.x; ov.y = fv.y + p.y;
            ov.z = fv.z + p.z; ov.w = fv.w + p.w;
            *reinterpret_cast<float4*>(&ob[d * HW + px4]) = ov;
        }
    }
}

// ============================================================================
extern "C" void kernel_launch(void* const* d_in, const int* in_sizes, int n_in,
                              void* d_out, int out_size) {
    const float* feature = (const float*)d_in[0];
    const float* token   = (const float*)d_in[1];
    const float* Wv      = (const float*)d_in[2];
    const float* bv      = (const float*)d_in[3];
    const float* Wk      = (const float*)d_in[4];
    const float* bk      = (const float*)d_in[5];
    float* out = (float*)d_out;

    vk_kernel<<<NB * CCH, 64>>>(token, Wv, bv, Wk, bk);
    attn_kernel<<<NB * NH * 128, 128>>>(feature, out);
}